// round 8
// baseline (speedup 1.0000x reference)
#include <cuda_runtime.h>
#include <cuda_fp16.h>
#include <cstdint>

typedef uint32_t u32;

// ---------------- device scratch (allocation-free rule) ----------------------
__device__ __align__(16) float g_planes[3 * 32 * 32 * 64]; // [plane][y][x][c]
__device__ __align__(16) u32   g_w1f[16 * 4 * 32 * 4];     // [nt][ks][lane][w] frag-packed
__device__ __align__(16) u32   g_w2f[16 * 8 * 32 * 4];     // [nt][ks][lane][w]

#define NW 16
// per-warp A1 region: 32 planes (ks*8+w; w 0-3 hi, 4-7 lo) x 32 lanes = 1024 u32
#define SMEM_U32_TOTAL (NW * 1024 + 384)
#define SMEM_BYTES (SMEM_U32_TOTAL * 4)

// scaling keeps fp16 residuals out of the denormal range
#define S1      16384.0f
#define INV_S1  (1.0f / 16384.0f)
#define S2      4096.0f
#define INV_S2  (1.0f / 4096.0f)
#define SC      2048.0f
#define INV_SC  (1.0f / 2048.0f)

// ---------------- helpers ----------------------------------------------------
__device__ __forceinline__ float2 ldcg2(const float* p) {
    float2 v; asm("ld.global.cg.v2.f32 {%0,%1}, [%2];" : "=f"(v.x), "=f"(v.y) : "l"(p)); return v;
}
__device__ __forceinline__ u32 pk2(float x, float y) {
    __half2 h = __halves2half2(__float2half_rn(x), __float2half_rn(y));
    return *(u32*)&h;
}
__device__ __forceinline__ float rf16(float x) {
    return __half2float(__float2half_rn(x));
}
__device__ __forceinline__ void mma16(float* c, const u32* a, u32 b0, u32 b1) {
    asm volatile("mma.sync.aligned.m16n8k16.row.col.f32.f16.f16.f32 "
        "{%0,%1,%2,%3}, {%4,%5,%6,%7}, {%8,%9}, {%0,%1,%2,%3};"
        : "+f"(c[0]), "+f"(c[1]), "+f"(c[2]), "+f"(c[3])
        : "r"(a[0]), "r"(a[1]), "r"(a[2]), "r"(a[3]), "r"(b0), "r"(b1));
}

// ---------------- prep: planes channel-last; weights frag-packed hi + lo*2048
__global__ void prep_kernel(const float* __restrict__ pxy, const float* __restrict__ pyz,
                            const float* __restrict__ pxz, const float* __restrict__ w1,
                            const float* __restrict__ w2) {
    int idx = blockIdx.x * 256 + threadIdx.x;
    if (idx < 196608) {
        int pl = idx >> 16;
        int r  = idx & 65535;
        const float* src = (pl == 0) ? pxy : ((pl == 1) ? pyz : pxz);
        float v = src[r];
        int c = r >> 10, y = (r >> 5) & 31, x = r & 31;
        g_planes[(pl << 16) + (((y << 5) + x) << 6) + c] = v;
    } else if (idx < 196608 + 8192) {
        int i = idx - 196608;                       // w1: [n=128][k=64]
        int w = i & 3, lane = (i >> 2) & 31, ks = (i >> 7) & 3, nt = i >> 9;
        int g = lane >> 2, t = lane & 3;
        int n = nt * 8 + g;
        int k0 = ks * 16 + ((w & 1) << 3) + t * 2;
        float v0 = w1[n * 64 + k0], v1 = w1[n * 64 + k0 + 1];
        u32 val = (w < 2) ? pk2(v0, v1)
                          : pk2((v0 - rf16(v0)) * SC, (v1 - rf16(v1)) * SC);
        g_w1f[i] = val;
    } else if (idx < 196608 + 8192 + 16384) {
        int i = idx - (196608 + 8192);              // w2: [n=128][k=128]
        int w = i & 3, lane = (i >> 2) & 31, ks = (i >> 7) & 7, nt = i >> 10;
        int g = lane >> 2, t = lane & 3;
        int n = nt * 8 + g;
        int k0 = ks * 16 + ((w & 1) << 3) + t * 2;
        float v0 = w2[n * 128 + k0], v1 = w2[n * 128 + k0 + 1];
        u32 val = (w < 2) ? pk2(v0, v1)
                          : pk2((v0 - rf16(v0)) * SC, (v1 - rf16(v1)) * SC);
        g_w2f[i] = val;
    }
}

// ---------------- axis-hoisted bilinear sampling ------------------------------
struct Ax { int i; float w0, w1; int v0, v1; };
__device__ __forceinline__ Ax mkax(float g) {
    Ax a;
    float x = (g + 1.0f) * 15.5f;     // matches reference rounding
    float f = floorf(x);
    a.i = (int)f;
    a.w1 = x - f; a.w0 = 1.0f - a.w1;
    a.v0 = ((unsigned)a.i < 32u);
    a.v1 = ((unsigned)(a.i + 1) < 32u);
    return a;
}
__device__ __forceinline__ float2 sampA(const float* __restrict__ base, const Ax X, const Ax Y) {
    float2 acc = make_float2(0.f, 0.f);
    const float* p = base + (((Y.i << 5) + X.i) << 6);
    if (X.v0 & Y.v0) { float w = X.w0 * Y.w0; float2 v = ldcg2(p);
        acc.x = fmaf(w, v.x, acc.x); acc.y = fmaf(w, v.y, acc.y); }
    if (X.v1 & Y.v0) { float w = X.w1 * Y.w0; float2 v = ldcg2(p + 64);
        acc.x = fmaf(w, v.x, acc.x); acc.y = fmaf(w, v.y, acc.y); }
    if (X.v0 & Y.v1) { float w = X.w0 * Y.w1; float2 v = ldcg2(p + 2048);
        acc.x = fmaf(w, v.x, acc.x); acc.y = fmaf(w, v.y, acc.y); }
    if (X.v1 & Y.v1) { float w = X.w1 * Y.w1; float2 v = ldcg2(p + 2112);
        acc.x = fmaf(w, v.x, acc.x); acc.y = fmaf(w, v.y, acc.y); }
    return acc;
}

// ---------------- persistent warp-autonomous fused kernel --------------------
__global__ __launch_bounds__(NW * 32, 1) void fused_kernel(
    const float* __restrict__ coords,
    const float* __restrict__ b1, const float* __restrict__ b2,
    const float* __restrict__ w3, const float* __restrict__ b3,
    float* __restrict__ out, int nslices)
{
    extern __shared__ __align__(16) u32 dsm[];
    float* sB1 = (float*)(dsm + NW * 1024);
    float* sB2 = sB1 + 128;
    float* sW3 = sB2 + 128;

    int tid = threadIdx.x, lane = tid & 31, wid = tid >> 5;
    if (tid < 128) { sB1[tid] = b1[tid]; sB2[tid] = b2[tid]; sW3[tid] = w3[tid]; }
    __syncthreads();

    u32* aw = dsm + wid * 1024;                 // this warp's A1 region

    int g = lane >> 2, t = lane & 3;
    float bb3 = __ldg(b3);
    const float* bs = g_planes + 2 * lane;
    const uint4* w1f = (const uint4*)g_w1f;
    const uint4* w2f = (const uint4*)g_w2f;

    // sampler-side constants (lane covers channels 2l, 2l+1)
    int ks_s   = lane >> 3;
    int whi2   = ((lane >> 2) & 1) * 2;         // w_hi = (r>>3) + whi2
    int tl     = lane & 3;
    int sswz   = ks_s * 4 + whi2 * 8;           // store-side bank swizzle (r-indep)

    int totalWarps = gridDim.x * NW;
    for (int s = blockIdx.x * NW + wid; s < nslices; s += totalWarps) {
        __syncwarp();
        int pbase = s * 16;

        // ---- sampling: 16 points, swizzled conflict-free stores -------------
        #pragma unroll 2
        for (int r = 0; r < 16; r++) {
            const float* cp = coords + 3 * (pbase + r);
            float c0 = __ldg(cp), c1 = __ldg(cp + 1), c2 = __ldg(cp + 2);
            Ax A0 = mkax(c0), A1 = mkax(c1), A2 = mkax(c2);
            float2 fxy = sampA(bs,          A0, A1);
            float2 fyz = sampA(bs + 65536,  A1, A2);
            float2 fxz = sampA(bs + 131072, A0, A2);
            float f0 = fxy.x * fyz.x * fxz.x * S1;
            float f1 = fxy.y * fyz.y * fxz.y * S1;
            int w_hi = (r >> 3) + whi2;
            int lcx  = (r & 7) * 4 + tl;
            int addr = (ks_s * 8 + w_hi) * 32 + (lcx ^ sswz);
            aw[addr]       = pk2(f0, f1);
            aw[addr + 128] = pk2((f0 - rf16(f0)) * SC, (f1 - rf16(f1)) * SC);
        }
        __syncwarp();

        // ---- load A1 fragments (swizzle-matched, conflict-free) -------------
        u32 ah[4][4], al[4][4];
        #pragma unroll
        for (int ks = 0; ks < 4; ks++)
            #pragma unroll
            for (int w = 0; w < 4; w++) {
                int bank = lane ^ (ks * 4) ^ ((w & 2) * 8);
                ah[ks][w] = aw[(ks * 8 + w) * 32 + bank];
                al[ks][w] = aw[(ks * 8 + w + 4) * 32 + bank];
            }

        // ---- layer 1: 16 n-tiles, K=64, 3 balanced chains -------------------
        u32 a2h[8][4], a2l[8][4];
        #pragma unroll 1
        for (int nt = 0; nt < 16; nt++) {
            float c0[4] = {0.f, 0.f, 0.f, 0.f};
            float c1[4] = {0.f, 0.f, 0.f, 0.f};
            float c2[4] = {0.f, 0.f, 0.f, 0.f};
            #pragma unroll
            for (int ks = 0; ks < 4; ks++) {
                uint4 B = __ldg(w1f + (nt * 4 + ks) * 32 + lane);
                mma16(c0, ah[ks], B.x, B.y);   // Ah*Bh
                mma16(c1, al[ks], B.x, B.y);   // (Al*SC)*Bh
                mma16(c2, ah[ks], B.z, B.w);   // Ah*(Bl*SC)
            }
            int n = nt * 8 + t * 2;
            float s0 = fmaf(c1[0] + c2[0], INV_SC, c0[0]);
            float s1 = fmaf(c1[1] + c2[1], INV_SC, c0[1]);
            float s2 = fmaf(c1[2] + c2[2], INV_SC, c0[2]);
            float s3 = fmaf(c1[3] + c2[3], INV_SC, c0[3]);
            float h0 = fmaxf(fmaf(s0, INV_S1, sB1[n]),     0.f) * S2;
            float h1 = fmaxf(fmaf(s1, INV_S1, sB1[n + 1]), 0.f) * S2;
            float h2 = fmaxf(fmaf(s2, INV_S1, sB1[n]),     0.f) * S2;
            float h3 = fmaxf(fmaf(s3, INV_S1, sB1[n + 1]), 0.f) * S2;
            int ks2 = nt >> 1, w0 = (nt & 1) * 2;
            a2h[ks2][w0]     = pk2(h0, h1);
            a2h[ks2][w0 + 1] = pk2(h2, h3);
            a2l[ks2][w0]     = pk2((h0 - rf16(h0)) * SC, (h1 - rf16(h1)) * SC);
            a2l[ks2][w0 + 1] = pk2((h2 - rf16(h2)) * SC, (h3 - rf16(h3)) * SC);
        }

        // ---- layer 2: 16 n-tiles, K=128, 3 balanced chains + fused layer-3 --
        float plo = 0.f, phi = 0.f;
        #pragma unroll 1
        for (int nt = 0; nt < 16; nt++) {
            float c0[4] = {0.f, 0.f, 0.f, 0.f};
            float c1[4] = {0.f, 0.f, 0.f, 0.f};
            float c2[4] = {0.f, 0.f, 0.f, 0.f};
            #pragma unroll
            for (int ks = 0; ks < 8; ks++) {
                uint4 B = __ldg(w2f + (nt * 8 + ks) * 32 + lane);
                mma16(c0, a2h[ks], B.x, B.y);
                mma16(c1, a2l[ks], B.x, B.y);
                mma16(c2, a2h[ks], B.z, B.w);
            }
            int n = nt * 8 + t * 2;
            float w30 = sW3[n], w31 = sW3[n + 1];
            float bb0 = sB2[n], bb1 = sB2[n + 1];
            float v0 = fmaf(fmaf(c1[0] + c2[0], INV_SC, c0[0]), INV_S2, bb0);
            float v1 = fmaf(fmaf(c1[1] + c2[1], INV_SC, c0[1]), INV_S2, bb1);
            float v2 = fmaf(fmaf(c1[2] + c2[2], INV_SC, c0[2]), INV_S2, bb0);
            float v3 = fmaf(fmaf(c1[3] + c2[3], INV_SC, c0[3]), INV_S2, bb1);
            plo = fmaf(fmaxf(v0, 0.f), w30, plo);
            plo = fmaf(fmaxf(v1, 0.f), w31, plo);
            phi = fmaf(fmaxf(v2, 0.f), w30, phi);
            phi = fmaf(fmaxf(v3, 0.f), w31, phi);
        }
        plo += __shfl_xor_sync(0xffffffffu, plo, 1);
        plo += __shfl_xor_sync(0xffffffffu, plo, 2);
        phi += __shfl_xor_sync(0xffffffffu, phi, 1);
        phi += __shfl_xor_sync(0xffffffffu, phi, 2);
        if (t == 0) {
            out[pbase + g]     = plo + bb3;
            out[pbase + g + 8] = phi + bb3;
        }
    }
}

// ---------------- launch ------------------------------------------------------
extern "C" void kernel_launch(void* const* d_in, const int* in_sizes, int n_in,
                              void* d_out, int out_size) {
    const float* coords = (const float*)d_in[0];
    const float* pxy    = (const float*)d_in[1];
    const float* pyz    = (const float*)d_in[2];
    const float* pxz    = (const float*)d_in[3];
    const float* w1     = (const float*)d_in[4];
    const float* b1     = (const float*)d_in[5];
    const float* w2     = (const float*)d_in[6];
    const float* b2     = (const float*)d_in[7];
    const float* w3     = (const float*)d_in[8];
    const float* b3     = (const float*)d_in[9];
    float* out = (float*)d_out;

    int M = in_sizes[0] / 3;       // 1048576
    int nslices = M / 16;          // 65536

    prep_kernel<<<864, 256>>>(pxy, pyz, pxz, w1, w2);

    int dev = 0, nsm = 148;
    cudaGetDevice(&dev);
    cudaDeviceGetAttribute(&nsm, cudaDevAttrMultiProcessorCount, dev);

    cudaFuncSetAttribute(fused_kernel, cudaFuncAttributeMaxDynamicSharedMemorySize, SMEM_BYTES);
    fused_kernel<<<nsm, NW * 32, SMEM_BYTES>>>(coords, b1, b2, w3, b3, out, nslices);
}

// round 9
// speedup vs baseline: 1.1166x; 1.1166x over previous
#include <cuda_runtime.h>
#include <cuda_fp16.h>
#include <cstdint>

typedef uint32_t u32;

// ---------------- device scratch (allocation-free rule) ----------------------
__device__ __align__(16) float g_planes[3 * 32 * 32 * 64]; // [plane][y][x][c]
__device__ __align__(16) u32   g_w1f[16 * 4 * 32 * 4];     // [nt][ks][lane][w] frag-packed
__device__ __align__(16) u32   g_w2f[16 * 8 * 32 * 4];     // [nt][ks][lane][w]

#define NW 16
// per-warp region: 1024 u32. Used for A1 staging, then reused for A2-lo.
#define SMEM_U32_TOTAL (NW * 1024 + 384)
#define SMEM_BYTES (SMEM_U32_TOTAL * 4)

// scaling keeps fp16 residuals out of the denormal range
#define S1      16384.0f
#define INV_S1  (1.0f / 16384.0f)
#define S2      4096.0f
#define INV_S2  (1.0f / 4096.0f)
#define SC      2048.0f
#define INV_SC  (1.0f / 2048.0f)

// ---------------- helpers ----------------------------------------------------
__device__ __forceinline__ u32 s2u(const void* p) {
    u32 a; asm("{ .reg .u64 t; cvta.to.shared.u64 t, %1; cvt.u32.u64 %0, t; }" : "=r"(a) : "l"(p)); return a;
}
__device__ __forceinline__ float2 ldcg2(const float* p) {
    float2 v; asm("ld.global.cg.v2.f32 {%0,%1}, [%2];" : "=f"(v.x), "=f"(v.y) : "l"(p)); return v;
}
__device__ __forceinline__ u32 pk2(float x, float y) {
    __half2 h = __halves2half2(__float2half_rn(x), __float2half_rn(y));
    return *(u32*)&h;
}
__device__ __forceinline__ float rf16(float x) {
    return __half2float(__float2half_rn(x));
}
__device__ __forceinline__ void mma16(float* c, const u32* a, u32 b0, u32 b1) {
    asm volatile("mma.sync.aligned.m16n8k16.row.col.f32.f16.f16.f32 "
        "{%0,%1,%2,%3}, {%4,%5,%6,%7}, {%8,%9}, {%0,%1,%2,%3};"
        : "+f"(c[0]), "+f"(c[1]), "+f"(c[2]), "+f"(c[3])
        : "r"(a[0]), "r"(a[1]), "r"(a[2]), "r"(a[3]), "r"(b0), "r"(b1));
}
// asm shared ops: volatile so LICM can't hoist the 8 per-nt LDS into 32 registers
__device__ __forceinline__ void sts64s(u32 addr, u32 a, u32 b) {
    asm volatile("st.shared.v2.u32 [%0], {%1,%2};" :: "r"(addr), "r"(a), "r"(b));
}
__device__ __forceinline__ uint4 lds128s(u32 addr) {
    uint4 v;
    asm volatile("ld.shared.v4.u32 {%0,%1,%2,%3}, [%4];"
        : "=r"(v.x), "=r"(v.y), "=r"(v.z), "=r"(v.w) : "r"(addr));
    return v;
}

// ---------------- prep: planes channel-last; weights frag-packed hi + lo*2048
__global__ void prep_kernel(const float* __restrict__ pxy, const float* __restrict__ pyz,
                            const float* __restrict__ pxz, const float* __restrict__ w1,
                            const float* __restrict__ w2) {
    int idx = blockIdx.x * 256 + threadIdx.x;
    if (idx < 196608) {
        int pl = idx >> 16;
        int r  = idx & 65535;
        const float* src = (pl == 0) ? pxy : ((pl == 1) ? pyz : pxz);
        float v = src[r];
        int c = r >> 10, y = (r >> 5) & 31, x = r & 31;
        g_planes[(pl << 16) + (((y << 5) + x) << 6) + c] = v;
    } else if (idx < 196608 + 8192) {
        int i = idx - 196608;                       // w1: [n=128][k=64]
        int w = i & 3, lane = (i >> 2) & 31, ks = (i >> 7) & 3, nt = i >> 9;
        int g = lane >> 2, t = lane & 3;
        int n = nt * 8 + g;
        int k0 = ks * 16 + ((w & 1) << 3) + t * 2;
        float v0 = w1[n * 64 + k0], v1 = w1[n * 64 + k0 + 1];
        u32 val = (w < 2) ? pk2(v0, v1)
                          : pk2((v0 - rf16(v0)) * SC, (v1 - rf16(v1)) * SC);
        g_w1f[i] = val;
    } else if (idx < 196608 + 8192 + 16384) {
        int i = idx - (196608 + 8192);              // w2: [n=128][k=128]
        int w = i & 3, lane = (i >> 2) & 31, ks = (i >> 7) & 7, nt = i >> 10;
        int g = lane >> 2, t = lane & 3;
        int n = nt * 8 + g;
        int k0 = ks * 16 + ((w & 1) << 3) + t * 2;
        float v0 = w2[n * 128 + k0], v1 = w2[n * 128 + k0 + 1];
        u32 val = (w < 2) ? pk2(v0, v1)
                          : pk2((v0 - rf16(v0)) * SC, (v1 - rf16(v1)) * SC);
        g_w2f[i] = val;
    }
}

// ---------------- axis-hoisted bilinear sampling ------------------------------
struct Ax { int i; float w0, w1; int v0, v1; };
__device__ __forceinline__ Ax mkax(float g) {
    Ax a;
    float x = (g + 1.0f) * 15.5f;     // matches reference rounding
    float f = floorf(x);
    a.i = (int)f;
    a.w1 = x - f; a.w0 = 1.0f - a.w1;
    a.v0 = ((unsigned)a.i < 32u);
    a.v1 = ((unsigned)(a.i + 1) < 32u);
    return a;
}
__device__ __forceinline__ float2 sampA(const float* __restrict__ base, const Ax X, const Ax Y) {
    float2 acc = make_float2(0.f, 0.f);
    const float* p = base + (((Y.i << 5) + X.i) << 6);
    if (X.v0 & Y.v0) { float w = X.w0 * Y.w0; float2 v = ldcg2(p);
        acc.x = fmaf(w, v.x, acc.x); acc.y = fmaf(w, v.y, acc.y); }
    if (X.v1 & Y.v0) { float w = X.w1 * Y.w0; float2 v = ldcg2(p + 64);
        acc.x = fmaf(w, v.x, acc.x); acc.y = fmaf(w, v.y, acc.y); }
    if (X.v0 & Y.v1) { float w = X.w0 * Y.w1; float2 v = ldcg2(p + 2048);
        acc.x = fmaf(w, v.x, acc.x); acc.y = fmaf(w, v.y, acc.y); }
    if (X.v1 & Y.v1) { float w = X.w1 * Y.w1; float2 v = ldcg2(p + 2112);
        acc.x = fmaf(w, v.x, acc.x); acc.y = fmaf(w, v.y, acc.y); }
    return acc;
}

// ---------------- persistent warp-autonomous fused kernel --------------------
__global__ __launch_bounds__(NW * 32, 1) void fused_kernel(
    const float* __restrict__ coords,
    const float* __restrict__ b1, const float* __restrict__ b2,
    const float* __restrict__ w3, const float* __restrict__ b3,
    float* __restrict__ out, int nslices)
{
    extern __shared__ __align__(16) u32 dsm[];
    float* sB1 = (float*)(dsm + NW * 1024);
    float* sB2 = sB1 + 128;
    float* sW3 = sB2 + 128;

    int tid = threadIdx.x, lane = tid & 31, wid = tid >> 5;
    if (tid < 128) { sB1[tid] = b1[tid]; sB2[tid] = b2[tid]; sW3[tid] = w3[tid]; }
    __syncthreads();

    u32* aw = dsm + wid * 1024;                   // warp-private region (C view)
    u32 awb = s2u(dsm) + wid * 4096;              // same region (shared-addr view)

    int g = lane >> 2, t = lane & 3;
    float bb3 = __ldg(b3);
    const float* bs = g_planes + 2 * lane;
    const uint4* w1f = (const uint4*)g_w1f;
    const uint4* w2f = (const uint4*)g_w2f;

    // sampler-side constants (lane covers channels 2l, 2l+1)
    int ks_s   = lane >> 3;
    int whi2   = ((lane >> 2) & 1) * 2;           // w_hi = (r>>3) + whi2
    int tl     = lane & 3;
    int sswz   = ks_s * 4 + whi2 * 8;             // store-side bank swizzle

    // A2-lo shared addressing (lane-local roundtrip, conflict-free)
    u32 loa = awb + lane * 16;                    // + ks*512 + w0*4

    int totalWarps = gridDim.x * NW;
    for (int s = blockIdx.x * NW + wid; s < nslices; s += totalWarps) {
        __syncwarp();
        int pbase = s * 16;

        // ---- sampling: 16 points, swizzled conflict-free stores -------------
        #pragma unroll 2
        for (int r = 0; r < 16; r++) {
            const float* cp = coords + 3 * (pbase + r);
            float c0 = __ldg(cp), c1 = __ldg(cp + 1), c2 = __ldg(cp + 2);
            Ax A0 = mkax(c0), A1 = mkax(c1), A2 = mkax(c2);
            float2 fxy = sampA(bs,          A0, A1);
            float2 fyz = sampA(bs + 65536,  A1, A2);
            float2 fxz = sampA(bs + 131072, A0, A2);
            float f0 = fxy.x * fyz.x * fxz.x * S1;
            float f1 = fxy.y * fyz.y * fxz.y * S1;
            int w_hi = (r >> 3) + whi2;
            int lcx  = (r & 7) * 4 + tl;
            int addr = (ks_s * 8 + w_hi) * 32 + (lcx ^ sswz);
            aw[addr]       = pk2(f0, f1);
            aw[addr + 128] = pk2((f0 - rf16(f0)) * SC, (f1 - rf16(f1)) * SC);
        }
        __syncwarp();

        // ---- load A1 fragments (swizzle-matched, conflict-free) -------------
        u32 ah[4][4], al[4][4];
        #pragma unroll
        for (int ks = 0; ks < 4; ks++)
            #pragma unroll
            for (int w = 0; w < 4; w++) {
                int bank = lane ^ (ks * 4) ^ ((w & 2) * 8);
                ah[ks][w] = aw[(ks * 8 + w) * 32 + bank];
                al[ks][w] = aw[(ks * 8 + w + 4) * 32 + bank];
            }
        __syncwarp();   // A1 region fully consumed; safe to overwrite with A2-lo

        // ---- layer 1: 16 n-tiles, K=64, 3 balanced chains, unroll 2 ---------
        u32 a2h[8][4];
        #pragma unroll 2
        for (int nt = 0; nt < 16; nt++) {
            float c0[4] = {0.f, 0.f, 0.f, 0.f};
            float c1[4] = {0.f, 0.f, 0.f, 0.f};
            float c2[4] = {0.f, 0.f, 0.f, 0.f};
            #pragma unroll
            for (int ks = 0; ks < 4; ks++) {
                uint4 B = __ldg(w1f + (nt * 4 + ks) * 32 + lane);
                mma16(c0, ah[ks], B.x, B.y);   // Ah*Bh
                mma16(c1, al[ks], B.x, B.y);   // (Al*SC)*Bh
                mma16(c2, ah[ks], B.z, B.w);   // Ah*(Bl*SC)
            }
            int n = nt * 8 + t * 2;
            float s0 = fmaf(c1[0] + c2[0], INV_SC, c0[0]);
            float s1 = fmaf(c1[1] + c2[1], INV_SC, c0[1]);
            float s2 = fmaf(c1[2] + c2[2], INV_SC, c0[2]);
            float s3 = fmaf(c1[3] + c2[3], INV_SC, c0[3]);
            float h0 = fmaxf(fmaf(s0, INV_S1, sB1[n]),     0.f) * S2;
            float h1 = fmaxf(fmaf(s1, INV_S1, sB1[n + 1]), 0.f) * S2;
            float h2 = fmaxf(fmaf(s2, INV_S1, sB1[n]),     0.f) * S2;
            float h3 = fmaxf(fmaf(s3, INV_S1, sB1[n + 1]), 0.f) * S2;
            int ks2 = nt >> 1, w0 = (nt & 1) * 2;
            a2h[ks2][w0]     = pk2(h0, h1);
            a2h[ks2][w0 + 1] = pk2(h2, h3);
            // A2-lo -> smem (frees 32 registers); lane-local, STS.64
            sts64s(loa + ks2 * 512 + w0 * 4,
                   pk2((h0 - rf16(h0)) * SC, (h1 - rf16(h1)) * SC),
                   pk2((h2 - rf16(h2)) * SC, (h3 - rf16(h3)) * SC));
        }

        // ---- layer 2: 16 n-tiles, K=128, 3 chains + streamed A-lo, unroll 2 -
        float plo = 0.f, phi = 0.f;
        #pragma unroll 2
        for (int nt = 0; nt < 16; nt++) {
            float c0[4] = {0.f, 0.f, 0.f, 0.f};
            float c1[4] = {0.f, 0.f, 0.f, 0.f};
            float c2[4] = {0.f, 0.f, 0.f, 0.f};
            #pragma unroll
            for (int ks = 0; ks < 8; ks++) {
                uint4 B  = __ldg(w2f + (nt * 8 + ks) * 32 + lane);
                uint4 lo = lds128s(loa + ks * 512);
                mma16(c0, a2h[ks], B.x, B.y);
                mma16(c1, (const u32*)&lo, B.x, B.y);
                mma16(c2, a2h[ks], B.z, B.w);
            }
            int n = nt * 8 + t * 2;
            float w30 = sW3[n], w31 = sW3[n + 1];
            float bb0 = sB2[n], bb1 = sB2[n + 1];
            float v0 = fmaf(fmaf(c1[0] + c2[0], INV_SC, c0[0]), INV_S2, bb0);
            float v1 = fmaf(fmaf(c1[1] + c2[1], INV_SC, c0[1]), INV_S2, bb1);
            float v2 = fmaf(fmaf(c1[2] + c2[2], INV_SC, c0[2]), INV_S2, bb0);
            float v3 = fmaf(fmaf(c1[3] + c2[3], INV_SC, c0[3]), INV_S2, bb1);
            plo = fmaf(fmaxf(v0, 0.f), w30, plo);
            plo = fmaf(fmaxf(v1, 0.f), w31, plo);
            phi = fmaf(fmaxf(v2, 0.f), w30, phi);
            phi = fmaf(fmaxf(v3, 0.f), w31, phi);
        }
        plo += __shfl_xor_sync(0xffffffffu, plo, 1);
        plo += __shfl_xor_sync(0xffffffffu, plo, 2);
        phi += __shfl_xor_sync(0xffffffffu, phi, 1);
        phi += __shfl_xor_sync(0xffffffffu, phi, 2);
        if (t == 0) {
            out[pbase + g]     = plo + bb3;
            out[pbase + g + 8] = phi + bb3;
        }
    }
}

// ---------------- launch ------------------------------------------------------
extern "C" void kernel_launch(void* const* d_in, const int* in_sizes, int n_in,
                              void* d_out, int out_size) {
    const float* coords = (const float*)d_in[0];
    const float* pxy    = (const float*)d_in[1];
    const float* pyz    = (const float*)d_in[2];
    const float* pxz    = (const float*)d_in[3];
    const float* w1     = (const float*)d_in[4];
    const float* b1     = (const float*)d_in[5];
    const float* w2     = (const float*)d_in[6];
    const float* b2     = (const float*)d_in[7];
    const float* w3     = (const float*)d_in[8];
    const float* b3     = (const float*)d_in[9];
    float* out = (float*)d_out;

    int M = in_sizes[0] / 3;       // 1048576
    int nslices = M / 16;          // 65536

    prep_kernel<<<864, 256>>>(pxy, pyz, pxz, w1, w2);

    int dev = 0, nsm = 148;
    cudaGetDevice(&dev);
    cudaDeviceGetAttribute(&nsm, cudaDevAttrMultiProcessorCount, dev);

    cudaFuncSetAttribute(fused_kernel, cudaFuncAttributeMaxDynamicSharedMemorySize, SMEM_BYTES);
    fused_kernel<<<nsm, NW * 32, SMEM_BYTES>>>(coords, b1, b2, w3, b3, out, nslices);
}